// round 15
// baseline (speedup 1.0000x reference)
#include <cuda_runtime.h>
#include <cuda_bf16.h>
#include <cstdint>

// Problem constants (fixed by the reference)
constexpr int cN   = 50000;
constexpr int cE   = 400000;
constexpr int cR   = 3;
constexpr int cH   = 3;
constexpr int cIN  = 128;
constexpr int cHID = 64;
constexpr int cOUT = 64;
constexpr int cC   = 16;
constexpr int cB   = 8;
constexpr int cF2  = cH * cHID;   // 192
constexpr int cM   = cN * cH;     // 150000
constexpr int cRN  = cR * cN;     // 150000
constexpr int cRE  = cR * cE;     // 1.2M
constexpr int SCAN_NB = (cRN + 1023) / 1024;  // 147

// ------------------------- device scratch (static, no alloc) -------------------------
__device__ int      g_outdeg[cRN];
__device__ int      g_indeg[cRN];
__device__ float    g_ns[cRN];
__device__ float    g_nd[cRN];
__device__ int      g_off[cRN + 1];
__device__ int      g_cursor[cRN];
__device__ int      g_bsum[256];
__device__ int      g_esrc[cRE];
__device__ int      g_edst[cRE];
__device__ float    g_ew[(size_t)cRE * 4];              // per-edge softmax weights
__device__ __nv_bfloat16 g_xWh[cRN * cHID];             // conv1 features, bf16
__device__ float    g_h1[cN * cHID];
__device__ __nv_bfloat16 g_fh[(size_t)cRN * cF2];       // GAT features, bf16
__device__ float    g_el4[cRN * 4];
__device__ float    g_er4[cRN * 4];
__device__ float    g_gat[cN * cF2];                    // pre-init w/ bias; relu in mm2
__device__ __nv_bfloat16 g_xW2h[(size_t)cR * cM * cOUT];// conv2 features, bf16 (ns-folded)
__device__ float    g_acc2[cM * cOUT];                  // pre-init w/ bias; sigmoid in pool
__device__ float    g_pool[cB * cF2];
__device__ float    g_cnt[cB];

__device__ __forceinline__ float sigmoidf_(float v) { return 1.f / (1.f + __expf(-v)); }
__device__ __forceinline__ void red2(float* p, float a, float b) {
    asm volatile("red.global.add.v2.f32 [%0], {%1,%2};" :: "l"(p), "f"(a), "f"(b) : "memory");
}

// tf32 round (rna)
__device__ __forceinline__ float tf32c(float x) {
    uint32_t o; asm("cvt.rna.tf32.f32 %0, %1;" : "=r"(o) : "f"(x));
    return __uint_as_float(o);
}
// m16n8k8 tf32 mma, fp32 accumulate
__device__ __forceinline__ void mma8(float* c, uint32_t a0, uint32_t a1, uint32_t a2,
                                     uint32_t a3, uint32_t b0, uint32_t b1) {
    asm volatile("mma.sync.aligned.m16n8k8.row.col.f32.tf32.tf32.f32 "
                 "{%0,%1,%2,%3}, {%4,%5,%6,%7}, {%8,%9}, {%0,%1,%2,%3};"
                 : "+f"(c[0]), "+f"(c[1]), "+f"(c[2]), "+f"(c[3])
                 : "r"(a0), "r"(a1), "r"(a2), "r"(a3), "r"(b0), "r"(b1));
}

// ------------------------- init -------------------------
__global__ void k_init0() {
    int i = blockIdx.x * blockDim.x + threadIdx.x;
    if (i < cRN) { g_outdeg[i] = 0; g_indeg[i] = 0; }
    if (i < cB * cF2) g_pool[i] = 0.f;
    if (i < cB)       g_cnt[i] = 0.f;
}
// bias pre-init for gather targets (side stream; only needs b1/bg/b2)
__global__ void k_binit(const float* __restrict__ b1, const float* __restrict__ bg,
                        const float* __restrict__ b2) {
    int i = blockIdx.x * blockDim.x + threadIdx.x;
    if (i >= cN * cF2) return;                        // == cM*cOUT
    int j = i % cF2;
    g_gat[i]  = bg[j] + bg[cF2 + j] + bg[2 * cF2 + j];
    int o = i % cOUT;
    g_acc2[i] = b2[o] + b2[cOUT + o] + b2[2 * cOUT + o];
    if (i < cN * cHID) {
        int jj = i % cHID;
        g_h1[i] = b1[jj] + b1[cHID + jj] + b1[2 * cHID + jj];
    }
}

// ------------------------- degrees -------------------------
__global__ void k_deg(const int* __restrict__ src, const int* __restrict__ dst) {
    int i = blockIdx.x * blockDim.x + threadIdx.x;
    if (i >= cRE) return;
    int r = i / cE;
    atomicAdd(&g_outdeg[r * cN + src[i]], 1);
    atomicAdd(&g_indeg[r * cN + dst[i]], 1);
}

// ------------------------- scan (fused degree->norm; scanC + node-count) -------------------------
__global__ void k_scanA() {
    __shared__ int wsum[8];
    int tid = threadIdx.x, lane = tid & 31, wid = tid >> 5;
    int idx0 = blockIdx.x * 1024 + tid * 4;
    int v[4]; int s = 0;
#pragma unroll
    for (int k = 0; k < 4; k++) {
        int i = idx0 + k;
        int x = (i < cRN) ? g_indeg[i] : 0;
        if (i < cRN) {
            g_nd[i] = rsqrtf(fmaxf((float)x, 1.f));
            g_ns[i] = rsqrtf(fmaxf((float)g_outdeg[i], 1.f));
        }
        v[k] = s; s += x;
    }
    int incl = s;
#pragma unroll
    for (int o = 1; o < 32; o <<= 1) {
        int t = __shfl_up_sync(0xffffffffu, incl, o);
        if (lane >= o) incl += t;
    }
    int excl = incl - s;
    if (lane == 31) wsum[wid] = incl;
    __syncthreads();
    if (tid == 0) {
        int a = 0;
#pragma unroll
        for (int w = 0; w < 8; w++) { int t = wsum[w]; wsum[w] = a; a += t; }
        g_bsum[blockIdx.x] = a;
    }
    __syncthreads();
    int base = wsum[wid] + excl;
#pragma unroll
    for (int k = 0; k < 4; k++) {
        int i = idx0 + k;
        if (i < cRN) g_off[i] = base + v[k];
    }
}
__global__ void k_scanB() {
    __shared__ int wsum[8];
    int tid = threadIdx.x, lane = tid & 31, wid = tid >> 5;
    int v = (tid < SCAN_NB) ? g_bsum[tid] : 0;
    int incl = v;
#pragma unroll
    for (int o = 1; o < 32; o <<= 1) {
        int t = __shfl_up_sync(0xffffffffu, incl, o);
        if (lane >= o) incl += t;
    }
    if (lane == 31) wsum[wid] = incl;
    __syncthreads();
    if (tid == 0) {
        int a = 0;
#pragma unroll
        for (int w = 0; w < 8; w++) { int t = wsum[w]; wsum[w] = a; a += t; }
    }
    __syncthreads();
    if (tid < SCAN_NB) g_bsum[tid] = wsum[wid] + incl - v;
}
__global__ void k_scanC(const int* __restrict__ gid) {
    int i = blockIdx.x * blockDim.x + threadIdx.x;
    if (i >= cRN) return;
    int o = g_off[i] + g_bsum[i >> 10];
    g_off[i] = o;
    g_cursor[i] = o;
    if (i == 0) g_off[cRN] = cRE;
    if (i < cN) {
        int g = gid[i];
        unsigned m = __match_any_sync(__activemask(), g);
        int leader = __ffs(m) - 1;
        if ((threadIdx.x & 31) == leader)
            atomicAdd(&g_cnt[g], (float)__popc(m));
    }
}
__global__ void k_fill(const int* __restrict__ src, const int* __restrict__ dst) {
    int i = blockIdx.x * blockDim.x + threadIdx.x;
    if (i >= cRE) return;
    int r = i / cE;
    int fd = r * cN + dst[i];
    int pos = atomicAdd(&g_cursor[fd], 1);
    g_esrc[pos] = src[i];
    g_edst[pos] = fd;
}

// ------------------------- per-edge softmax weights (post-mmF) -------------------------
__global__ void k_edgew() {
    int i = blockIdx.x * blockDim.x + threadIdx.x;
    if (i >= cRE) return;
    int d = g_edst[i];
    int r = d / cN;
    int sflat = r * cN + g_esrc[i];
    float4 el = __ldg((const float4*)g_el4 + sflat);
    float4 er = __ldg((const float4*)g_er4 + d);
    float e0 = el.x + er.x, e1 = el.y + er.y, e2 = el.z + er.z;
    e0 = e0 > 0.f ? e0 : 0.2f * e0;
    e1 = e1 > 0.f ? e1 : 0.2f * e1;
    e2 = e2 > 0.f ? e2 : 0.2f * e2;
    ((float4*)g_ew)[i] = make_float4(__expf(e0), __expf(e1), __expf(e2), 0.f);
}

// ------------------------- tf32 mma.sync GEMM (K-blocked) ---------------------------------------
template<int K, int LDB, bool ATT, bool BF, int NSDIV, bool RELU>
__global__ void __launch_bounds__(128) k_hmm(
    const float* __restrict__ A, const float* __restrict__ Bsrc,
    const float* __restrict__ al, const float* __restrict__ ar,
    void* __restrict__ Cout, int rows)
{
    __shared__ float sA[64][68];
    __shared__ float sB[64][72];
    __shared__ float sAl[2][64];
    int tid = threadIdx.x, warp = tid >> 5, lane = tid & 31;
    int gid = lane >> 2, tig = lane & 3;
    int r = blockIdx.y, ct = blockIdx.z;
    int n0 = blockIdx.x * 64;

    if (ATT && tid < 64) {
        sAl[0][tid] = __ldg(&al[r * 192 + ct * 64 + tid]);
        sAl[1][tid] = __ldg(&ar[r * 192 + ct * 64 + tid]);
    }

    int r0 = warp * 16;
    float c[8][4];
#pragma unroll
    for (int t = 0; t < 8; t++)
#pragma unroll
        for (int j = 0; j < 4; j++) c[t][j] = 0.f;

    const float* Ab = A + (size_t)n0 * K;
    const float* Bb = Bsrc + (size_t)r * K * LDB + ct * 64;

#pragma unroll
    for (int kb = 0; kb < K; kb += 64) {
        if (kb) __syncthreads();
        for (int i = tid; i < 64 * 16; i += 128) {
            int row = i >> 4, c4 = (i & 15) * 4;
            float4 v = (n0 + row < rows)
                ? __ldg((const float4*)(Ab + (size_t)row * K + kb + c4))
                : make_float4(0.f, 0.f, 0.f, 0.f);
            if (RELU) {
                v.x = fmaxf(v.x, 0.f); v.y = fmaxf(v.y, 0.f);
                v.z = fmaxf(v.z, 0.f); v.w = fmaxf(v.w, 0.f);
            }
            sA[row][c4]     = tf32c(v.x);
            sA[row][c4 + 1] = tf32c(v.y);
            sA[row][c4 + 2] = tf32c(v.z);
            sA[row][c4 + 3] = tf32c(v.w);
        }
        for (int i = tid; i < 64 * 16; i += 128) {
            int k = i >> 4, c4 = (i & 15) * 4;
            float4 v = __ldg((const float4*)(Bb + (size_t)(kb + k) * LDB + c4));
            sB[k][c4]     = tf32c(v.x);
            sB[k][c4 + 1] = tf32c(v.y);
            sB[k][c4 + 2] = tf32c(v.z);
            sB[k][c4 + 3] = tf32c(v.w);
        }
        __syncthreads();
#pragma unroll
        for (int kt = 0; kt < 8; kt++) {
            int k0 = kt * 8;
            uint32_t a0 = __float_as_uint(sA[r0 + gid][k0 + tig]);
            uint32_t a1 = __float_as_uint(sA[r0 + gid + 8][k0 + tig]);
            uint32_t a2 = __float_as_uint(sA[r0 + gid][k0 + tig + 4]);
            uint32_t a3 = __float_as_uint(sA[r0 + gid + 8][k0 + tig + 4]);
#pragma unroll
            for (int t = 0; t < 8; t++) {
                uint32_t b0 = __float_as_uint(sB[k0 + tig][t * 8 + gid]);
                uint32_t b1 = __float_as_uint(sB[k0 + tig + 4][t * 8 + gid]);
                mma8(c[t], a0, a1, a2, a3, b0, b1);
            }
        }
    }

    int row0 = n0 + r0 + gid, row1 = row0 + 8;
    size_t base = (size_t)r * rows;
    float s0 = 1.f, s1 = 1.f;
    if (NSDIV) {
        if (row0 < rows) s0 = __ldg(&g_ns[r * cN + row0 / NSDIV]);
        if (row1 < rows) s1 = __ldg(&g_ns[r * cN + row1 / NSDIV]);
    }
#pragma unroll
    for (int t = 0; t < 8; t++) {
        int col = ct * 64 + t * 8 + tig * 2;
        if (BF) {
            __nv_bfloat16* Cb = (__nv_bfloat16*)Cout;
            if (row0 < rows) *(__nv_bfloat162*)(Cb + (base + row0) * LDB + col) =
                __floats2bfloat162_rn(c[t][0] * s0, c[t][1] * s0);
            if (row1 < rows) *(__nv_bfloat162*)(Cb + (base + row1) * LDB + col) =
                __floats2bfloat162_rn(c[t][2] * s1, c[t][3] * s1);
        } else {
            float* Cf = (float*)Cout;
            if (row0 < rows) *(float2*)(Cf + (base + row0) * LDB + col) = make_float2(c[t][0], c[t][1]);
            if (row1 < rows) *(float2*)(Cf + (base + row1) * LDB + col) = make_float2(c[t][2], c[t][3]);
        }
    }

    if (ATT) {
        float pl0 = 0.f, pl1 = 0.f, pr0 = 0.f, pr1 = 0.f;
#pragma unroll
        for (int t = 0; t < 8; t++) {
            float l0 = sAl[0][t * 8 + tig * 2], l1 = sAl[0][t * 8 + tig * 2 + 1];
            float q0 = sAl[1][t * 8 + tig * 2], q1 = sAl[1][t * 8 + tig * 2 + 1];
            pl0 += c[t][0] * l0 + c[t][1] * l1;
            pl1 += c[t][2] * l0 + c[t][3] * l1;
            pr0 += c[t][0] * q0 + c[t][1] * q1;
            pr1 += c[t][2] * q0 + c[t][3] * q1;
        }
#pragma unroll
        for (int o = 1; o < 4; o <<= 1) {
            pl0 += __shfl_xor_sync(0xffffffffu, pl0, o);
            pl1 += __shfl_xor_sync(0xffffffffu, pl1, o);
            pr0 += __shfl_xor_sync(0xffffffffu, pr0, o);
            pr1 += __shfl_xor_sync(0xffffffffu, pr1, o);
        }
        if (tig == 0) {
            if (row0 < rows) { g_el4[(r * cN + row0) * 4 + ct] = pl0; g_er4[(r * cN + row0) * 4 + ct] = pr0; }
            if (row1 < rows) { g_el4[(r * cN + row1) * 4 + ct] = pl1; g_er4[(r * cN + row1) * 4 + ct] = pr1; }
        }
    }
}

// ------------------------- conv1 gather: warp per (node, relation), red into g_h1 -------------------------
__global__ void __launch_bounds__(256) k_gath1() {
    int gw = blockIdx.x * 8 + (threadIdx.x >> 5);
    int lane = threadIdx.x & 31;
    if (gw >= cRN) return;
    int idx = gw;
    int r = idx / cN;
    int n = idx - r * cN;
    int rb = r * cN;
    float nd = g_nd[idx];
    float2 t = {0.f, 0.f};
#define G1_BODY(J) { \
    int s_ = __ldg(&g_esrc[J]); \
    float sc_ = __ldg(&g_ns[rb + s_]); \
    float2 v_ = __bfloat1622float2(__ldg((const __nv_bfloat162*)(g_xWh + (size_t)(rb + s_) * 64) + lane)); \
    t.x += sc_ * v_.x; t.y += sc_ * v_.y; }
    int beg = g_off[idx], end = g_off[idx + 1];
    int j = beg;
    for (; j + 4 <= end; j += 4) { G1_BODY(j) G1_BODY(j + 1) G1_BODY(j + 2) G1_BODY(j + 3) }
    for (; j < end; ++j) { G1_BODY(j) }
#undef G1_BODY
    if (t.x != 0.f || t.y != 0.f || true)
        red2(g_h1 + (size_t)n * 64 + lane * 2, nd * t.x, nd * t.y);
}

// ------------------------- L2 row normalize -------------------------
__global__ void __launch_bounds__(256) k_l2n() {
    int n = blockIdx.x * 8 + (threadIdx.x >> 5);
    int lane = threadIdx.x & 31;
    if (n >= cN) return;
    float2* p = (float2*)(g_h1 + (size_t)n * 64) + lane;
    float2 a = *p;
    float ss = a.x * a.x + a.y * a.y;
#pragma unroll
    for (int o = 16; o; o >>= 1) ss += __shfl_xor_sync(0xffffffffu, ss, o);
    float inv = 1.f / fmaxf(sqrtf(ss), 1e-12f);
    p->x = a.x * inv; p->y = a.y * inv;
}

// ------------------------- GAT gather: warp per (node, relation), red into g_gat -------------------------
__global__ void __launch_bounds__(256) k_ggat() {
    int gw = blockIdx.x * 8 + (threadIdx.x >> 5);
    int lane = threadIdx.x & 31;
    if (gw >= cRN) return;
    int idx = gw;
    int r = idx / cN;
    int n = idx - r * cN;
    int rb = r * cN;
    float z0 = 0.f, z1 = 0.f, z2 = 0.f;
    float2 t0 = {0.f, 0.f}, t1 = {0.f, 0.f}, t2 = {0.f, 0.f};
#define GG_BODY(J) { \
    int s_ = __ldg(&g_esrc[J]); \
    float4 w_ = __ldg((const float4*)g_ew + (J)); \
    const __nv_bfloat162* fr_ = (const __nv_bfloat162*)(g_fh + (size_t)(rb + s_) * 192); \
    float2 f0_ = __bfloat1622float2(__ldg(fr_ + lane)); \
    float2 f1_ = __bfloat1622float2(__ldg(fr_ + 32 + lane)); \
    float2 f2_ = __bfloat1622float2(__ldg(fr_ + 64 + lane)); \
    z0 += w_.x; z1 += w_.y; z2 += w_.z; \
    t0.x += w_.x * f0_.x; t0.y += w_.x * f0_.y; \
    t1.x += w_.y * f1_.x; t1.y += w_.y * f1_.y; \
    t2.x += w_.z * f2_.x; t2.y += w_.z * f2_.y; }
    int beg = g_off[idx], end = g_off[idx + 1];
    int j = beg;
    for (; j + 4 <= end; j += 4) { GG_BODY(j) GG_BODY(j + 1) GG_BODY(j + 2) GG_BODY(j + 3) }
    for (; j < end; ++j) { GG_BODY(j) }
#undef GG_BODY
    float r0 = 1.f / (z0 + 1e-9f), r1 = 1.f / (z1 + 1e-9f), r2 = 1.f / (z2 + 1e-9f);
    float* o = g_gat + (size_t)n * 192 + lane * 2;
    red2(o,       t0.x * r0, t0.y * r0);
    red2(o + 64,  t1.x * r1, t1.y * r1);
    red2(o + 128, t2.x * r2, t2.y * r2);
}

// ------------------------- conv2 gather: warp per (node, relation), red into g_acc2 -------------------------
__global__ void __launch_bounds__(256) k_gath2() {
    int gw = blockIdx.x * 8 + (threadIdx.x >> 5);
    int lane = threadIdx.x & 31;
    if (gw >= cRN) return;
    int idx = gw;
    int r = idx / cN;
    int n = idx - r * cN;
    float nd = g_nd[idx];
    float2 t0 = {0.f, 0.f}, t1 = {0.f, 0.f}, t2 = {0.f, 0.f};
#define G2_BODY(J) { \
    int s_ = __ldg(&g_esrc[J]); \
    const __nv_bfloat162* base_ = (const __nv_bfloat162*)(g_xW2h + ((size_t)r * cM + (size_t)s_ * 3) * 64); \
    float2 f0_ = __bfloat1622float2(__ldg(base_ + lane)); \
    float2 f1_ = __bfloat1622float2(__ldg(base_ + 32 + lane)); \
    float2 f2_ = __bfloat1622float2(__ldg(base_ + 64 + lane)); \
    t0.x += f0_.x; t0.y += f0_.y; \
    t1.x += f1_.x; t1.y += f1_.y; \
    t2.x += f2_.x; t2.y += f2_.y; }
    int beg = g_off[idx], end = g_off[idx + 1];
    int j = beg;
    for (; j + 4 <= end; j += 4) { G2_BODY(j) G2_BODY(j + 1) G2_BODY(j + 2) G2_BODY(j + 3) }
    for (; j < end; ++j) { G2_BODY(j) }
#undef G2_BODY
    float* o = g_acc2 + (size_t)n * 192 + lane * 2;
    red2(o,       nd * t0.x, nd * t0.y);
    red2(o + 64,  nd * t1.x, nd * t1.y);
    red2(o + 128, nd * t2.x, nd * t2.y);
}

// ------------------------- graph pooling (sigmoid fused here) -------------------------
__global__ void k_pool(const int* __restrict__ gid) {
    int n0 = blockIdx.x * 64;
    int j  = threadIdx.x;                        // 192 threads
    int curg = -1;
    float a = 0.f;
#pragma unroll 1
    for (int m = 0; m < 64; m++) {
        int n = n0 + m;
        if (n >= cN) break;
        int g = __ldg(&gid[n]);
        float v = sigmoidf_(g_acc2[(size_t)n * 192 + j]);
        if (g != curg) {
            if (curg >= 0) atomicAdd(&g_pool[curg * 192 + j], a);
            curg = g; a = 0.f;
        }
        a += v;
    }
    if (curg >= 0) atomicAdd(&g_pool[curg * 192 + j], a);
}

// ------------------------- final classifier + mean -------------------------
__global__ void k_final(const float* __restrict__ Wc, const float* __restrict__ bc,
                        float* __restrict__ out) {
    int t = threadIdx.x;                          // 384 threads
    int b = t / 48, rem = t % 48, h = rem / 16, c = rem & 15;
    float inv = 1.f / fmaxf(g_cnt[b], 1.f);
    const float* P = g_pool + (b * 3 + h) * 64;
    float dot = bc[c];
#pragma unroll
    for (int k = 0; k < 64; k++) dot += P[k] * inv * Wc[k * 16 + c];
    float sg = 1.f / (1.f + expf(-dot));
#pragma unroll
    for (int off = 8; off; off >>= 1) sg += __shfl_xor_sync(0xffffffffu, sg, off);
    if (c == 0) out[b * 3 + h] = sg * (1.f / 16.f);
}

// ------------------------- launcher -------------------------
extern "C" void kernel_launch(void* const* d_in, const int* in_sizes, int n_in,
                              void* d_out, int out_size) {
    const float* x   = (const float*)d_in[0];
    const int*   src = (const int*)  d_in[1];
    const int*   dst = (const int*)  d_in[2];
    const int*   gid = (const int*)  d_in[3];
    const float* W1  = (const float*)d_in[4];
    const float* b1  = (const float*)d_in[5];
    const float* Wg  = (const float*)d_in[6];
    const float* al  = (const float*)d_in[7];
    const float* ar  = (const float*)d_in[8];
    const float* bg  = (const float*)d_in[9];
    const float* W2  = (const float*)d_in[10];
    const float* b2  = (const float*)d_in[11];
    const float* Wc  = (const float*)d_in[12];
    const float* bc  = (const float*)d_in[13];
    float* out = (float*)d_out;

    void *vxWh, *vh1, *vfh, *vgat, *vxW2h;
    cudaGetSymbolAddress(&vxWh,  g_xWh);
    cudaGetSymbolAddress(&vh1,   g_h1);
    cudaGetSymbolAddress(&vfh,   g_fh);
    cudaGetSymbolAddress(&vgat,  g_gat);
    cudaGetSymbolAddress(&vxW2h, g_xW2h);
    const float* ph1  = (const float*)vh1;
    const float* pgat = (const float*)vgat;

    static cudaStream_t s2 = nullptr;
    static cudaEvent_t ev_fork = nullptr, ev_join = nullptr;
    if (!s2) {
        cudaStreamCreateWithFlags(&s2, cudaStreamNonBlocking);
        cudaEventCreateWithFlags(&ev_fork, cudaEventDisableTiming);
        cudaEventCreateWithFlags(&ev_join, cudaEventDisableTiming);
    }

    // fork: mm1 + bias pre-init on side stream (hidden under CSR build)
    cudaEventRecord(ev_fork, 0);
    cudaStreamWaitEvent(s2, ev_fork, 0);
    k_hmm<128, 64, false, true, 0, false><<<dim3((cN + 63) / 64, 3, 1), 128, 0, s2>>>(
        x, W1, nullptr, nullptr, vxWh, cN);
    k_binit<<<(cN * cF2 + 255) / 256, 256, 0, s2>>>(b1, bg, b2);
    cudaEventRecord(ev_join, s2);

    // main: CSR build
    k_init0<<<(cRN + 255) / 256, 256>>>();
    k_deg<<<(cRE + 255) / 256, 256>>>(src, dst);
    k_scanA<<<SCAN_NB, 256>>>();
    k_scanB<<<1, 256>>>();
    k_scanC<<<(cRN + 255) / 256, 256>>>(gid);
    k_fill<<<(cRE + 255) / 256, 256>>>(src, dst);

    // join
    cudaStreamWaitEvent(0, ev_join, 0);
    k_gath1<<<(cRN + 7) / 8, 256>>>();
    k_l2n<<<(cN + 7) / 8, 256>>>();

    // GAT
    k_hmm<64, 192, true, true, 0, false><<<dim3((cN + 63) / 64, 3, 3), 128>>>(ph1, Wg, al, ar, vfh, cN);
    k_edgew<<<(cRE + 255) / 256, 256>>>();
    k_ggat<<<(cRN + 7) / 8, 256>>>();

    // layer 2 (relu folded into A-load; ns folded into epilogue)
    k_hmm<64, 64, false, true, 3, true><<<dim3((cM + 63) / 64, 3, 1), 128>>>(pgat, W2, nullptr, nullptr, vxW2h, cM);
    k_gath2<<<(cRN + 7) / 8, 256>>>();

    // pooling + classifier
    k_pool<<<(cN + 63) / 64, 192>>>(gid);
    k_final<<<1, 384>>>(Wc, bc, out);
}

// round 16
// speedup vs baseline: 1.0715x; 1.0715x over previous
#include <cuda_runtime.h>
#include <cuda_fp16.h>
#include <cstdint>

// Problem constants (fixed by the reference)
constexpr int cN   = 50000;
constexpr int cE   = 400000;
constexpr int cR   = 3;
constexpr int cH   = 3;
constexpr int cIN  = 128;
constexpr int cHID = 64;
constexpr int cOUT = 64;
constexpr int cC   = 16;
constexpr int cB   = 8;
constexpr int cF2  = cH * cHID;   // 192
constexpr int cM   = cN * cH;     // 150000
constexpr int cRN  = cR * cN;     // 150000
constexpr int cRE  = cR * cE;     // 1.2M
constexpr int SCAN_NB = (cRN + 1023) / 1024;  // 147

// ------------------------- device scratch (static, no alloc) -------------------------
__device__ int      g_outdeg[cRN];
__device__ int      g_indeg[cRN];
__device__ float    g_ns[cRN];
__device__ float    g_nd[cRN];
__device__ int      g_off[cRN + 1];
__device__ int      g_cursor[cRN];
__device__ int      g_bsum[256];
__device__ int2     g_edge[cRE];                        // {src, flat dst} per CSR slot
__device__ float    g_ew[(size_t)cRE * 4];              // per-edge softmax weights
__device__ uint8_t  g_xWh[cRN * cHID];                  // conv1 features, fp8 e4m3
__device__ float    g_h1[cN * cHID];
__device__ uint8_t  g_fh[(size_t)cRN * cF2];            // GAT features, fp8 e4m3
__device__ float    g_el4[cRN * 4];
__device__ float    g_er4[cRN * 4];
__device__ float    g_gat[cN * cF2];                    // relu'd GAT out, fp32
__device__ uint8_t  g_xW2h[(size_t)cR * cM * cOUT];     // conv2 features, fp8 (ns-folded)
__device__ float    g_acc2[cM * cOUT];                  // sigmoid(conv2 out)
__device__ float    g_pool[cB * cF2];
__device__ float    g_cnt[cB];

__device__ __forceinline__ float sigmoidf_(float v) { return 1.f / (1.f + __expf(-v)); }

// fp8 e4m3 pack/unpack (sm_89+ PTX, arch-agnostic through compute_103)
__device__ __forceinline__ unsigned short f2tofp8(float lo, float hi) {
    unsigned short r;
    asm("cvt.rn.satfinite.e4m3x2.f32 %0, %1, %2;" : "=h"(r) : "f"(hi), "f"(lo));
    return r;
}
__device__ __forceinline__ float2 fp8tof2(unsigned short u) {
    unsigned h2;
    asm("cvt.rn.f16x2.e4m3x2 %0, %1;" : "=r"(h2) : "h"(u));
    return __half22float2(*(half2*)&h2);
}

// tf32 round (rna)
__device__ __forceinline__ float tf32c(float x) {
    uint32_t o; asm("cvt.rna.tf32.f32 %0, %1;" : "=r"(o) : "f"(x));
    return __uint_as_float(o);
}
// m16n8k8 tf32 mma, fp32 accumulate
__device__ __forceinline__ void mma8(float* c, uint32_t a0, uint32_t a1, uint32_t a2,
                                     uint32_t a3, uint32_t b0, uint32_t b1) {
    asm volatile("mma.sync.aligned.m16n8k8.row.col.f32.tf32.tf32.f32 "
                 "{%0,%1,%2,%3}, {%4,%5,%6,%7}, {%8,%9}, {%0,%1,%2,%3};"
                 : "+f"(c[0]), "+f"(c[1]), "+f"(c[2]), "+f"(c[3])
                 : "r"(a0), "r"(a1), "r"(a2), "r"(a3), "r"(b0), "r"(b1));
}

// ------------------------- init -------------------------
__global__ void k_init0() {
    int i = blockIdx.x * blockDim.x + threadIdx.x;
    if (i < cRN) { g_outdeg[i] = 0; g_indeg[i] = 0; }
    if (i < cB * cF2) g_pool[i] = 0.f;
    if (i < cB)       g_cnt[i] = 0.f;
}

// ------------------------- degrees -------------------------
__global__ void k_deg(const int* __restrict__ src, const int* __restrict__ dst) {
    int i = blockIdx.x * blockDim.x + threadIdx.x;
    if (i >= cRE) return;
    int r = i / cE;
    atomicAdd(&g_outdeg[r * cN + src[i]], 1);
    atomicAdd(&g_indeg[r * cN + dst[i]], 1);
}

// ------------------------- scan (fused degree->norm; scanC + node-count) -------------------------
__global__ void k_scanA() {
    __shared__ int wsum[8];
    int tid = threadIdx.x, lane = tid & 31, wid = tid >> 5;
    int idx0 = blockIdx.x * 1024 + tid * 4;
    int v[4]; int s = 0;
#pragma unroll
    for (int k = 0; k < 4; k++) {
        int i = idx0 + k;
        int x = (i < cRN) ? g_indeg[i] : 0;
        if (i < cRN) {
            g_nd[i] = rsqrtf(fmaxf((float)x, 1.f));
            g_ns[i] = rsqrtf(fmaxf((float)g_outdeg[i], 1.f));
        }
        v[k] = s; s += x;
    }
    int incl = s;
#pragma unroll
    for (int o = 1; o < 32; o <<= 1) {
        int t = __shfl_up_sync(0xffffffffu, incl, o);
        if (lane >= o) incl += t;
    }
    int excl = incl - s;
    if (lane == 31) wsum[wid] = incl;
    __syncthreads();
    if (tid == 0) {
        int a = 0;
#pragma unroll
        for (int w = 0; w < 8; w++) { int t = wsum[w]; wsum[w] = a; a += t; }
        g_bsum[blockIdx.x] = a;
    }
    __syncthreads();
    int base = wsum[wid] + excl;
#pragma unroll
    for (int k = 0; k < 4; k++) {
        int i = idx0 + k;
        if (i < cRN) g_off[i] = base + v[k];
    }
}
__global__ void k_scanB() {
    __shared__ int wsum[8];
    int tid = threadIdx.x, lane = tid & 31, wid = tid >> 5;
    int v = (tid < SCAN_NB) ? g_bsum[tid] : 0;
    int incl = v;
#pragma unroll
    for (int o = 1; o < 32; o <<= 1) {
        int t = __shfl_up_sync(0xffffffffu, incl, o);
        if (lane >= o) incl += t;
    }
    if (lane == 31) wsum[wid] = incl;
    __syncthreads();
    if (tid == 0) {
        int a = 0;
#pragma unroll
        for (int w = 0; w < 8; w++) { int t = wsum[w]; wsum[w] = a; a += t; }
    }
    __syncthreads();
    if (tid < SCAN_NB) g_bsum[tid] = wsum[wid] + incl - v;
}
__global__ void k_scanC(const int* __restrict__ gid) {
    int i = blockIdx.x * blockDim.x + threadIdx.x;
    if (i >= cRN) return;
    int o = g_off[i] + g_bsum[i >> 10];
    g_off[i] = o;
    g_cursor[i] = o;
    if (i == 0) g_off[cRN] = cRE;
    if (i < cN) {
        int g = gid[i];
        unsigned m = __match_any_sync(__activemask(), g);
        int leader = __ffs(m) - 1;
        if ((threadIdx.x & 31) == leader)
            atomicAdd(&g_cnt[g], (float)__popc(m));
    }
}
__global__ void k_fill(const int* __restrict__ src, const int* __restrict__ dst) {
    int i = blockIdx.x * blockDim.x + threadIdx.x;
    if (i >= cRE) return;
    int r = i / cE;
    int fd = r * cN + dst[i];
    int pos = atomicAdd(&g_cursor[fd], 1);
    g_edge[pos] = make_int2(src[i], fd);
}

// ------------------------- per-edge softmax weights (post-mmF) -------------------------
__global__ void k_edgew() {
    int i = blockIdx.x * blockDim.x + threadIdx.x;
    if (i >= cRE) return;
    int2 e = g_edge[i];
    int d = e.y;
    int r = d / cN;
    int sflat = r * cN + e.x;
    float4 el = __ldg((const float4*)g_el4 + sflat);
    float4 er = __ldg((const float4*)g_er4 + d);
    float e0 = el.x + er.x, e1 = el.y + er.y, e2 = el.z + er.z;
    e0 = e0 > 0.f ? e0 : 0.2f * e0;
    e1 = e1 > 0.f ? e1 : 0.2f * e1;
    e2 = e2 > 0.f ? e2 : 0.2f * e2;
    ((float4*)g_ew)[i] = make_float4(__expf(e0), __expf(e1), __expf(e2), 0.f);
}

// ------------------------- tf32 mma.sync GEMM (K-blocked) ---------------------------------------
// OUTT: 0 = f32 out, 2 = fp8 e4m3 out.  NSDIV: scale row m by g_ns[r*cN + m/NSDIV].
template<int K, int LDB, bool ATT, int OUTT, int NSDIV>
__global__ void __launch_bounds__(128) k_hmm(
    const float* __restrict__ A, const float* __restrict__ Bsrc,
    const float* __restrict__ al, const float* __restrict__ ar,
    void* __restrict__ Cout, int rows)
{
    __shared__ float sA[64][68];
    __shared__ float sB[64][72];
    __shared__ float sAl[2][64];
    int tid = threadIdx.x, warp = tid >> 5, lane = tid & 31;
    int gid = lane >> 2, tig = lane & 3;
    int r = blockIdx.y, ct = blockIdx.z;
    int n0 = blockIdx.x * 64;

    if (ATT && tid < 64) {
        sAl[0][tid] = __ldg(&al[r * 192 + ct * 64 + tid]);
        sAl[1][tid] = __ldg(&ar[r * 192 + ct * 64 + tid]);
    }

    int r0 = warp * 16;
    float c[8][4];
#pragma unroll
    for (int t = 0; t < 8; t++)
#pragma unroll
        for (int j = 0; j < 4; j++) c[t][j] = 0.f;

    const float* Ab = A + (size_t)n0 * K;
    const float* Bb = Bsrc + (size_t)r * K * LDB + ct * 64;

#pragma unroll
    for (int kb = 0; kb < K; kb += 64) {
        if (kb) __syncthreads();
        for (int i = tid; i < 64 * 16; i += 128) {
            int row = i >> 4, c4 = (i & 15) * 4;
            float4 v = (n0 + row < rows)
                ? __ldg((const float4*)(Ab + (size_t)row * K + kb + c4))
                : make_float4(0.f, 0.f, 0.f, 0.f);
            sA[row][c4]     = tf32c(v.x);
            sA[row][c4 + 1] = tf32c(v.y);
            sA[row][c4 + 2] = tf32c(v.z);
            sA[row][c4 + 3] = tf32c(v.w);
        }
        for (int i = tid; i < 64 * 16; i += 128) {
            int k = i >> 4, c4 = (i & 15) * 4;
            float4 v = __ldg((const float4*)(Bb + (size_t)(kb + k) * LDB + c4));
            sB[k][c4]     = tf32c(v.x);
            sB[k][c4 + 1] = tf32c(v.y);
            sB[k][c4 + 2] = tf32c(v.z);
            sB[k][c4 + 3] = tf32c(v.w);
        }
        __syncthreads();
#pragma unroll
        for (int kt = 0; kt < 8; kt++) {
            int k0 = kt * 8;
            uint32_t a0 = __float_as_uint(sA[r0 + gid][k0 + tig]);
            uint32_t a1 = __float_as_uint(sA[r0 + gid + 8][k0 + tig]);
            uint32_t a2 = __float_as_uint(sA[r0 + gid][k0 + tig + 4]);
            uint32_t a3 = __float_as_uint(sA[r0 + gid + 8][k0 + tig + 4]);
#pragma unroll
            for (int t = 0; t < 8; t++) {
                uint32_t b0 = __float_as_uint(sB[k0 + tig][t * 8 + gid]);
                uint32_t b1 = __float_as_uint(sB[k0 + tig + 4][t * 8 + gid]);
                mma8(c[t], a0, a1, a2, a3, b0, b1);
            }
        }
    }

    int row0 = n0 + r0 + gid, row1 = row0 + 8;
    size_t base = (size_t)r * rows;
    float s0 = 1.f, s1 = 1.f;
    if (NSDIV) {
        if (row0 < rows) s0 = __ldg(&g_ns[r * cN + row0 / NSDIV]);
        if (row1 < rows) s1 = __ldg(&g_ns[r * cN + row1 / NSDIV]);
    }
#pragma unroll
    for (int t = 0; t < 8; t++) {
        int col = ct * 64 + t * 8 + tig * 2;
        if (OUTT == 2) {
            uint8_t* Cb = (uint8_t*)Cout;
            if (row0 < rows) *(unsigned short*)(Cb + (base + row0) * LDB + col) =
                f2tofp8(c[t][0] * s0, c[t][1] * s0);
            if (row1 < rows) *(unsigned short*)(Cb + (base + row1) * LDB + col) =
                f2tofp8(c[t][2] * s1, c[t][3] * s1);
        } else {
            float* Cf = (float*)Cout;
            if (row0 < rows) *(float2*)(Cf + (base + row0) * LDB + col) = make_float2(c[t][0], c[t][1]);
            if (row1 < rows) *(float2*)(Cf + (base + row1) * LDB + col) = make_float2(c[t][2], c[t][3]);
        }
    }

    if (ATT) {
        float pl0 = 0.f, pl1 = 0.f, pr0 = 0.f, pr1 = 0.f;
#pragma unroll
        for (int t = 0; t < 8; t++) {
            float l0 = sAl[0][t * 8 + tig * 2], l1 = sAl[0][t * 8 + tig * 2 + 1];
            float q0 = sAl[1][t * 8 + tig * 2], q1 = sAl[1][t * 8 + tig * 2 + 1];
            pl0 += c[t][0] * l0 + c[t][1] * l1;
            pl1 += c[t][2] * l0 + c[t][3] * l1;
            pr0 += c[t][0] * q0 + c[t][1] * q1;
            pr1 += c[t][2] * q0 + c[t][3] * q1;
        }
#pragma unroll
        for (int o = 1; o < 4; o <<= 1) {
            pl0 += __shfl_xor_sync(0xffffffffu, pl0, o);
            pl1 += __shfl_xor_sync(0xffffffffu, pl1, o);
            pr0 += __shfl_xor_sync(0xffffffffu, pr0, o);
            pr1 += __shfl_xor_sync(0xffffffffu, pr1, o);
        }
        if (tig == 0) {
            if (row0 < rows) { g_el4[(r * cN + row0) * 4 + ct] = pl0; g_er4[(r * cN + row0) * 4 + ct] = pr0; }
            if (row1 < rows) { g_el4[(r * cN + row1) * 4 + ct] = pl1; g_er4[(r * cN + row1) * 4 + ct] = pr1; }
        }
    }
}

// ------------------------- conv1 gather + L2 normalize (fp8 features) -------------------------
__global__ void __launch_bounds__(256) k_gath1(const float* __restrict__ b1) {
    int gw = blockIdx.x * 8 + (threadIdx.x >> 5);
    int lane = threadIdx.x & 31;
    if (gw >= cN) return;
    int n = gw;
    int p = lane * 2;
    float2 a;
    a.x = b1[p]     + b1[64 + p]     + b1[128 + p];
    a.y = b1[p + 1] + b1[64 + p + 1] + b1[128 + p + 1];
#define G1_BODY(J) { \
    int s_ = __ldg((const int*)&g_edge[J].x); \
    float sc_ = __ldg(&g_ns[rb + s_]) * nd; \
    float2 v_ = fp8tof2(__ldg((const unsigned short*)(g_xWh + (size_t)(rb + s_) * 64) + lane)); \
    a.x += sc_ * v_.x; a.y += sc_ * v_.y; }
#pragma unroll
    for (int r = 0; r < 3; r++) {
        int idx = r * cN + n;
        int rb = r * cN;
        float nd = g_nd[idx];
        int beg = g_off[idx], end = g_off[idx + 1];
        int j = beg;
        for (; j + 4 <= end; j += 4) { G1_BODY(j) G1_BODY(j + 1) G1_BODY(j + 2) G1_BODY(j + 3) }
        for (; j < end; ++j) { G1_BODY(j) }
    }
#undef G1_BODY
    float ss = a.x * a.x + a.y * a.y;
#pragma unroll
    for (int o = 16; o; o >>= 1) ss += __shfl_xor_sync(0xffffffffu, ss, o);
    float inv = 1.f / fmaxf(sqrtf(ss), 1e-12f);
    float2* outp = (float2*)(g_h1 + (size_t)n * 64) + lane;
    outp->x = a.x * inv; outp->y = a.y * inv;
}

// ------------------------- GAT gather: precomputed weights + fp8 features + relu -------------------------
__global__ void __launch_bounds__(256) k_ggat(const float* __restrict__ bg) {
    int gw = blockIdx.x * 8 + (threadIdx.x >> 5);
    int lane = threadIdx.x & 31;
    if (gw >= cN) return;
    int n = gw;
    int p = lane * 2;
    float2 acc0, acc1, acc2;
    acc0.x = bg[p]          + bg[192 + p]          + bg[384 + p];
    acc0.y = bg[p + 1]      + bg[192 + p + 1]      + bg[384 + p + 1];
    acc1.x = bg[64 + p]     + bg[256 + p]          + bg[448 + p];
    acc1.y = bg[64 + p + 1] + bg[256 + p + 1]      + bg[448 + p + 1];
    acc2.x = bg[128 + p]    + bg[320 + p]          + bg[512 + p];
    acc2.y = bg[128 + p + 1]+ bg[320 + p + 1]      + bg[512 + p + 1];
#define GG_BODY(J) { \
    int s_ = __ldg((const int*)&g_edge[J].x); \
    float4 w_ = __ldg((const float4*)g_ew + (J)); \
    const unsigned short* fr_ = (const unsigned short*)(g_fh + (size_t)(rb + s_) * 192); \
    float2 f0_ = fp8tof2(__ldg(fr_ + lane)); \
    float2 f1_ = fp8tof2(__ldg(fr_ + 32 + lane)); \
    float2 f2_ = fp8tof2(__ldg(fr_ + 64 + lane)); \
    z0 += w_.x; z1 += w_.y; z2 += w_.z; \
    t0.x += w_.x * f0_.x; t0.y += w_.x * f0_.y; \
    t1.x += w_.y * f1_.x; t1.y += w_.y * f1_.y; \
    t2.x += w_.z * f2_.x; t2.y += w_.z * f2_.y; }
#pragma unroll
    for (int r = 0; r < 3; r++) {
        int idx = r * cN + n;
        int rb = r * cN;
        float z0 = 0.f, z1 = 0.f, z2 = 0.f;
        float2 t0 = {0.f, 0.f}, t1 = {0.f, 0.f}, t2 = {0.f, 0.f};
        int beg = g_off[idx], end = g_off[idx + 1];
        int j = beg;
        for (; j + 4 <= end; j += 4) { GG_BODY(j) GG_BODY(j + 1) GG_BODY(j + 2) GG_BODY(j + 3) }
        for (; j < end; ++j) { GG_BODY(j) }
        float r0 = 1.f / (z0 + 1e-9f), r1 = 1.f / (z1 + 1e-9f), r2 = 1.f / (z2 + 1e-9f);
        acc0.x += t0.x * r0; acc0.y += t0.y * r0;
        acc1.x += t1.x * r1; acc1.y += t1.y * r1;
        acc2.x += t2.x * r2; acc2.y += t2.y * r2;
    }
#undef GG_BODY
    float2* o0 = (float2*)(g_gat + (size_t)n * 192)       + lane;
    float2* o1 = (float2*)(g_gat + (size_t)n * 192 + 64)  + lane;
    float2* o2 = (float2*)(g_gat + (size_t)n * 192 + 128) + lane;
    o0->x = fmaxf(acc0.x, 0.f); o0->y = fmaxf(acc0.y, 0.f);
    o1->x = fmaxf(acc1.x, 0.f); o1->y = fmaxf(acc1.y, 0.f);
    o2->x = fmaxf(acc2.x, 0.f); o2->y = fmaxf(acc2.y, 0.f);
}

// ------------------------- conv2 gather + sigmoid (fp8, ns folded, nd hoisted) -------------------------
__global__ void __launch_bounds__(256) k_gath2(const float* __restrict__ b2) {
    int gw = blockIdx.x * 8 + (threadIdx.x >> 5);
    int lane = threadIdx.x & 31;
    if (gw >= cN) return;
    int n = gw;
    int p = lane * 2;
    float bx = b2[p]     + b2[64 + p]     + b2[128 + p];
    float by = b2[p + 1] + b2[64 + p + 1] + b2[128 + p + 1];
    float2 acc0 = {bx, by}, acc1 = {bx, by}, acc2 = {bx, by};
#define G2_BODY(J) { \
    int s_ = __ldg((const int*)&g_edge[J].x); \
    const unsigned short* base_ = (const unsigned short*)(g_xW2h + ((size_t)r * cM + (size_t)s_ * 3) * 64); \
    float2 f0_ = fp8tof2(__ldg(base_ + lane)); \
    float2 f1_ = fp8tof2(__ldg(base_ + 32 + lane)); \
    float2 f2_ = fp8tof2(__ldg(base_ + 64 + lane)); \
    t0.x += f0_.x; t0.y += f0_.y; \
    t1.x += f1_.x; t1.y += f1_.y; \
    t2.x += f2_.x; t2.y += f2_.y; }
#pragma unroll
    for (int r = 0; r < 3; r++) {
        int idx = r * cN + n;
        float2 t0 = {0.f, 0.f}, t1 = {0.f, 0.f}, t2 = {0.f, 0.f};
        int beg = g_off[idx], end = g_off[idx + 1];
        int j = beg;
        for (; j + 4 <= end; j += 4) { G2_BODY(j) G2_BODY(j + 1) G2_BODY(j + 2) G2_BODY(j + 3) }
        for (; j < end; ++j) { G2_BODY(j) }
        float nd = g_nd[idx];
        acc0.x += nd * t0.x; acc0.y += nd * t0.y;
        acc1.x += nd * t1.x; acc1.y += nd * t1.y;
        acc2.x += nd * t2.x; acc2.y += nd * t2.y;
    }
#undef G2_BODY
    float2* o0 = (float2*)(g_acc2 + (size_t)n * 192)       + lane;
    float2* o1 = (float2*)(g_acc2 + (size_t)n * 192 + 64)  + lane;
    float2* o2 = (float2*)(g_acc2 + (size_t)n * 192 + 128) + lane;
    o0->x = sigmoidf_(acc0.x); o0->y = sigmoidf_(acc0.y);
    o1->x = sigmoidf_(acc1.x); o1->y = sigmoidf_(acc1.y);
    o2->x = sigmoidf_(acc2.x); o2->y = sigmoidf_(acc2.y);
}

// ------------------------- graph pooling (acc2 already sigmoid'd) -------------------------
__global__ void k_pool(const int* __restrict__ gid) {
    int n0 = blockIdx.x * 64;
    int j  = threadIdx.x;                        // 192 threads
    int curg = -1;
    float a = 0.f;
#pragma unroll 1
    for (int m = 0; m < 64; m++) {
        int n = n0 + m;
        if (n >= cN) break;
        int g = __ldg(&gid[n]);
        float v = g_acc2[(size_t)n * 192 + j];
        if (g != curg) {
            if (curg >= 0) atomicAdd(&g_pool[curg * 192 + j], a);
            curg = g; a = 0.f;
        }
        a += v;
    }
    if (curg >= 0) atomicAdd(&g_pool[curg * 192 + j], a);
}

// ------------------------- final classifier + mean -------------------------
__global__ void k_final(const float* __restrict__ Wc, const float* __restrict__ bc,
                        float* __restrict__ out) {
    int t = threadIdx.x;                          // 384 threads
    int b = t / 48, rem = t % 48, h = rem / 16, c = rem & 15;
    float inv = 1.f / fmaxf(g_cnt[b], 1.f);
    const float* P = g_pool + (b * 3 + h) * 64;
    float dot = bc[c];
#pragma unroll
    for (int k = 0; k < 64; k++) dot += P[k] * inv * Wc[k * 16 + c];
    float sg = 1.f / (1.f + expf(-dot));
#pragma unroll
    for (int off = 8; off; off >>= 1) sg += __shfl_xor_sync(0xffffffffu, sg, off);
    if (c == 0) out[b * 3 + h] = sg * (1.f / 16.f);
}

// ------------------------- launcher -------------------------
extern "C" void kernel_launch(void* const* d_in, const int* in_sizes, int n_in,
                              void* d_out, int out_size) {
    const float* x   = (const float*)d_in[0];
    const int*   src = (const int*)  d_in[1];
    const int*   dst = (const int*)  d_in[2];
    const int*   gid = (const int*)  d_in[3];
    const float* W1  = (const float*)d_in[4];
    const float* b1  = (const float*)d_in[5];
    const float* Wg  = (const float*)d_in[6];
    const float* al  = (const float*)d_in[7];
    const float* ar  = (const float*)d_in[8];
    const float* bg  = (const float*)d_in[9];
    const float* W2  = (const float*)d_in[10];
    const float* b2  = (const float*)d_in[11];
    const float* Wc  = (const float*)d_in[12];
    const float* bc  = (const float*)d_in[13];
    float* out = (float*)d_out;

    void *vxWh, *vh1, *vfh, *vgat, *vxW2h;
    cudaGetSymbolAddress(&vxWh,  g_xWh);
    cudaGetSymbolAddress(&vh1,   g_h1);
    cudaGetSymbolAddress(&vfh,   g_fh);
    cudaGetSymbolAddress(&vgat,  g_gat);
    cudaGetSymbolAddress(&vxW2h, g_xW2h);
    const float* ph1  = (const float*)vh1;
    const float* pgat = (const float*)vgat;

    static cudaStream_t s2 = nullptr;
    static cudaEvent_t ev_fork = nullptr, ev_join = nullptr;
    if (!s2) {
        cudaStreamCreateWithFlags(&s2, cudaStreamNonBlocking);
        cudaEventCreateWithFlags(&ev_fork, cudaEventDisableTiming);
        cudaEventCreateWithFlags(&ev_join, cudaEventDisableTiming);
    }

    // fork: mm1 (x @ W1) via tf32 mma -> fp8 features, on side stream
    cudaEventRecord(ev_fork, 0);
    cudaStreamWaitEvent(s2, ev_fork, 0);
    k_hmm<128, 64, false, 2, 0><<<dim3((cN + 63) / 64, 3, 1), 128, 0, s2>>>(
        x, W1, nullptr, nullptr, vxWh, cN);
    cudaEventRecord(ev_join, s2);

    // main: CSR build
    k_init0<<<(cRN + 255) / 256, 256>>>();
    k_deg<<<(cRE + 255) / 256, 256>>>(src, dst);
    k_scanA<<<SCAN_NB, 256>>>();
    k_scanB<<<1, 256>>>();
    k_scanC<<<(cRN + 255) / 256, 256>>>(gid);
    k_fill<<<(cRE + 255) / 256, 256>>>(src, dst);

    // join
    cudaStreamWaitEvent(0, ev_join, 0);
    k_gath1<<<(cN + 7) / 8, 256>>>(b1);

    // GAT
    k_hmm<64, 192, true, 2, 0><<<dim3((cN + 63) / 64, 3, 3), 128>>>(ph1, Wg, al, ar, vfh, cN);
    k_edgew<<<(cRE + 255) / 256, 256>>>();
    k_ggat<<<(cN + 7) / 8, 256>>>(bg);

    // layer 2 (ns folded into fp8 epilogue)
    k_hmm<64, 64, false, 2, 3><<<dim3((cM + 63) / 64, 3, 1), 128>>>(pgat, W2, nullptr, nullptr, vxW2h, cM);
    k_gath2<<<(cN + 7) / 8, 256>>>(b2);

    // pooling + classifier
    k_pool<<<(cN + 63) / 64, 192>>>(gid);
    k_final<<<1, 384>>>(Wc, bc, out);
}